// round 2
// baseline (speedup 1.0000x reference)
#include <cuda_runtime.h>
#include <math.h>

#define BSZ  1024
#define TLEN 256
#define HH   128
#define GG   384   // 3*H

// -------- scratch (static device globals; no runtime allocation) --------
__device__ float g_gi[(size_t)BSZ * TLEN * GG];    // 402 MB, reused for gi0 then gi1
__device__ float g_seq[(size_t)BSZ * TLEN * HH];   // 134 MB, layer-0 output sequence
__device__ float g_hlast[(size_t)BSZ * HH];        // layer-1 final hidden

// =======================================================================
// GEMM: g_gi[row][c] = sum_k X[row][k] * W[c][k] + bias[c]
// rows = 262144 (b*T+t), N = 384, K in {153,128}. 64-row tile, 256 threads,
// thread tile 8 rows x 12 cols. K chunked by 16 through shared memory.
// =======================================================================
__global__ void __launch_bounds__(256) gemm384(
    const float* __restrict__ Xext, int useSeq, int K,
    const float* __restrict__ W, const float* __restrict__ bias)
{
    const float* __restrict__ X = useSeq ? g_seq : Xext;
    __shared__ float xs[64][16];     // [row][kk]
    __shared__ float ws[16][385];    // [kk][col], padded row -> conflict-free STS
    int tid = threadIdx.x;
    size_t row0 = (size_t)blockIdx.x * 64;
    int tr = (tid >> 5) * 8;     // thread row base within tile
    int tc = tid & 31;           // thread col base; cols tc + 32*j

    float acc[8][12];
#pragma unroll
    for (int r = 0; r < 8; r++)
#pragma unroll
        for (int j = 0; j < 12; j++) acc[r][j] = 0.f;

    for (int k0 = 0; k0 < K; k0 += 16) {
        // load x chunk (coalesced global, conflict-free STS)
#pragma unroll
        for (int i = tid; i < 64 * 16; i += 256) {
            int r = i >> 4, kk = i & 15;
            int k = k0 + kk;
            xs[r][kk] = (k < K) ? X[(row0 + r) * (size_t)K + k] : 0.f;
        }
        // load W chunk transposed
#pragma unroll
        for (int i = tid; i < 384 * 16; i += 256) {
            int c = i >> 4, kk = i & 15;
            int k = k0 + kk;
            ws[kk][c] = (k < K) ? W[(size_t)c * K + k] : 0.f;
        }
        __syncthreads();
#pragma unroll
        for (int kk = 0; kk < 16; kk++) {
            float xv[8], wv[12];
#pragma unroll
            for (int r = 0; r < 8; r++) xv[r] = xs[tr + r][kk];  // broadcast
#pragma unroll
            for (int j = 0; j < 12; j++) wv[j] = ws[kk][tc + 32 * j];
#pragma unroll
            for (int r = 0; r < 8; r++)
#pragma unroll
                for (int j = 0; j < 12; j++)
                    acc[r][j] = fmaf(xv[r], wv[j], acc[r][j]);
        }
        __syncthreads();
    }
#pragma unroll
    for (int j = 0; j < 12; j++) {
        float bv = bias[tc + 32 * j];
#pragma unroll
        for (int r = 0; r < 8; r++)
            g_gi[(row0 + tr + r) * (size_t)GG + tc + 32 * j] = acc[r][j] + bv;
    }
}

// =======================================================================
// GRU recurrence. 128 CTAs x 8 batch rows; 256 threads. W_hh (fp32) lives
// transposed in shared memory (197 KB). Per step: gh = h @ W_hh^T via
// 2-row x 6-col thread tiles; gates computed after smem staging.
// writeSeq=1: write full sequence (layer 0). writeSeq=0: write h_last.
// =======================================================================
#define RECUR_SMEM ((128 * 385 + 8 * 128 + 8 * 384) * (int)sizeof(float))

__global__ void __launch_bounds__(256) gru_recur(
    const float* __restrict__ Whh, const float* __restrict__ bhh, int writeSeq)
{
    extern __shared__ float smem[];
    float* whT  = smem;                  // [128][385]  (Whh transposed, padded)
    float* hsh  = smem + 128 * 385;      // [8][128]    hidden state, row-major
    float* ghsh = hsh + 8 * 128;         // [8][384]    gh staging

    int tid = threadIdx.x;
    size_t b0 = (size_t)blockIdx.x * 8;

    // load Whh transposed: whT[k][g] = Whh[g][k]  (coalesced LDG, stride-385 STS)
    for (int idx = tid; idx < GG * HH; idx += 256) {
        int g = idx >> 7, k = idx & 127;
        whT[k * 385 + g] = Whh[idx];
    }
    for (int idx = tid; idx < 8 * HH; idx += 256) hsh[idx] = 0.f;

    // --- gh-compute mapping: 2 rows x 6 cols per thread ---
    int cg = tid & 63;            // col base; cols cg + 64*m, m<6
    int rp = tid >> 6;            // 0..3
    int r0 = rp * 2;              // rows r0, r0+1
    // --- gate-stage mapping: 1 row x 4 units per thread ---
    int gr = tid >> 5;            // 0..7 (uniform per warp)
    int gj = (tid & 31) * 4;      // unit base

    float bh[6];
#pragma unroll
    for (int m = 0; m < 6; m++) bh[m] = bhh[cg + 64 * m];

    float hreg[4] = {0.f, 0.f, 0.f, 0.f};
    __syncthreads();

    const float* gi_base = g_gi + ((b0 + gr) * TLEN) * (size_t)GG + gj;
    float* seq_base = g_seq + ((b0 + gr) * TLEN) * (size_t)HH + gj;

    for (int t = 0; t < TLEN; t++) {
        // prefetch this step's input-projection gates (hidden under gh loop)
        float4 gir = *(const float4*)(gi_base + (size_t)t * GG);
        float4 giz = *(const float4*)(gi_base + (size_t)t * GG + 128);
        float4 gin = *(const float4*)(gi_base + (size_t)t * GG + 256);

        float acc[2][6];
#pragma unroll
        for (int m = 0; m < 6; m++) { acc[0][m] = bh[m]; acc[1][m] = bh[m]; }

#pragma unroll 8
        for (int k = 0; k < HH; k++) {
            float h0 = hsh[r0 * HH + k];         // broadcast
            float h1 = hsh[(r0 + 1) * HH + k];   // broadcast
#pragma unroll
            for (int m = 0; m < 6; m++) {
                float w = whT[k * 385 + cg + 64 * m];  // conflict-free
                acc[0][m] = fmaf(h0, w, acc[0][m]);
                acc[1][m] = fmaf(h1, w, acc[1][m]);
            }
        }
#pragma unroll
        for (int m = 0; m < 6; m++) {
            ghsh[r0 * GG + cg + 64 * m]       = acc[0][m];
            ghsh[(r0 + 1) * GG + cg + 64 * m] = acc[1][m];
        }
        __syncthreads();

        // gate nonlinearity for 4 hidden units of row gr
        float4 ghr = *(float4*)(ghsh + gr * GG + gj);
        float4 ghz = *(float4*)(ghsh + gr * GG + 128 + gj);
        float4 ghn = *(float4*)(ghsh + gr * GG + 256 + gj);
        float ir[4] = {gir.x, gir.y, gir.z, gir.w};
        float iz[4] = {giz.x, giz.y, giz.z, giz.w};
        float in_[4] = {gin.x, gin.y, gin.z, gin.w};
        float hr[4] = {ghr.x, ghr.y, ghr.z, ghr.w};
        float hz[4] = {ghz.x, ghz.y, ghz.z, ghz.w};
        float hnn[4] = {ghn.x, ghn.y, ghn.z, ghn.w};
        float hn[4];
#pragma unroll
        for (int u = 0; u < 4; u++) {
            float r = 1.f / (1.f + expf(-(ir[u] + hr[u])));
            float z = 1.f / (1.f + expf(-(iz[u] + hz[u])));
            float n = tanhf(in_[u] + r * hnn[u]);
            hn[u] = (1.f - z) * n + z * hreg[u];
            hreg[u] = hn[u];
        }
        *(float4*)(hsh + gr * HH + gj) = make_float4(hn[0], hn[1], hn[2], hn[3]);
        if (writeSeq)
            *(float4*)(seq_base + (size_t)t * HH) = make_float4(hn[0], hn[1], hn[2], hn[3]);
        __syncthreads();
    }

    if (!writeSeq)
        *(float4*)(g_hlast + (b0 + gr) * HH + gj) =
            make_float4(hreg[0], hreg[1], hreg[2], hreg[3]);
}

// =======================================================================
// Head: out[b] = sigmoid( relu(h_last[b] @ W1^T + b1) @ W2^T + b2 )
// =======================================================================
__global__ void __launch_bounds__(64) head_kernel(
    const float* __restrict__ W1, const float* __restrict__ b1,
    const float* __restrict__ W2, const float* __restrict__ b2,
    float* __restrict__ out)
{
    int b = blockIdx.x;
    int c = threadIdx.x;  // 0..63
    const float* hb = g_hlast + (size_t)b * HH;
    const float* wr = W1 + (size_t)c * HH;
    float acc = b1[c];
#pragma unroll
    for (int k = 0; k < HH; k += 4) {
        float4 hv = *(const float4*)(hb + k);
        float4 wv = *(const float4*)(wr + k);
        acc = fmaf(hv.x, wv.x, acc);
        acc = fmaf(hv.y, wv.y, acc);
        acc = fmaf(hv.z, wv.z, acc);
        acc = fmaf(hv.w, wv.w, acc);
    }
    float v = fmaxf(acc, 0.f) * W2[c];
    __shared__ float red[64];
    red[c] = v;
    __syncthreads();
    if (c == 0) {
        float s = b2[0];
#pragma unroll
        for (int i = 0; i < 64; i++) s += red[i];
        out[b] = 1.f / (1.f + expf(-s));
    }
}

// =======================================================================
extern "C" void kernel_launch(void* const* d_in, const int* in_sizes, int n_in,
                              void* d_out, int out_size)
{
    const float* x     = (const float*)d_in[0];
    const float* W_ih0 = (const float*)d_in[1];
    const float* W_hh0 = (const float*)d_in[2];
    const float* b_ih0 = (const float*)d_in[3];
    const float* b_hh0 = (const float*)d_in[4];
    const float* W_ih1 = (const float*)d_in[5];
    const float* W_hh1 = (const float*)d_in[6];
    const float* b_ih1 = (const float*)d_in[7];
    const float* b_hh1 = (const float*)d_in[8];
    const float* W1    = (const float*)d_in[9];
    const float* b1    = (const float*)d_in[10];
    const float* W2    = (const float*)d_in[11];
    const float* b2    = (const float*)d_in[12];
    float* out = (float*)d_out;

    cudaFuncSetAttribute(gru_recur, cudaFuncAttributeMaxDynamicSharedMemorySize,
                         RECUR_SMEM);

    const int M_TILES = (BSZ * TLEN) / 64;  // 4096

    // layer 0 input projection: gi0 = x @ W_ih0^T + b_ih0
    gemm384<<<M_TILES, 256>>>(x, 0, 153, W_ih0, b_ih0);
    // layer 0 recurrence -> g_seq
    gru_recur<<<128, 256, RECUR_SMEM>>>(W_hh0, b_hh0, 1);
    // layer 1 input projection: gi1 = seq0 @ W_ih1^T + b_ih1 (reuses g_gi)
    gemm384<<<M_TILES, 256>>>(nullptr, 1, 128, W_ih1, b_ih1);
    // layer 1 recurrence -> g_hlast
    gru_recur<<<128, 256, RECUR_SMEM>>>(W_hh1, b_hh1, 0);
    // classifier head
    head_kernel<<<BSZ, 64>>>(W1, b1, W2, b2, out);
}

// round 5
// speedup vs baseline: 1.0534x; 1.0534x over previous
#include <cuda_runtime.h>
#include <math.h>

#define BSZ  1024
#define TLEN 256
#define HH   128
#define GG   384   // 3*H

// -------- scratch (static device globals; no runtime allocation) --------
__device__ float g_gi[(size_t)BSZ * TLEN * GG];    // 402 MB, reused for gi0 then gi1
__device__ float g_seq[(size_t)BSZ * TLEN * HH];   // 134 MB, layer-0 output sequence
__device__ float g_hlast[(size_t)BSZ * HH];        // layer-1 final hidden

typedef unsigned long long u64;

// ---- packed f32x2 helpers (sm_100+; ptxas never auto-fuses these) ----
__device__ __forceinline__ void fma2(u64& d, u64 a, u64 b) {
    asm("fma.rn.f32x2 %0, %1, %2, %0;" : "+l"(d) : "l"(a), "l"(b));
}
__device__ __forceinline__ u64 pack2(float x) {
    u64 r; asm("mov.b64 %0, {%1, %1};" : "=l"(r) : "f"(x)); return r;
}
__device__ __forceinline__ u64 pack2f(float x, float y) {
    u64 r; asm("mov.b64 %0, {%1, %2};" : "=l"(r) : "f"(x), "f"(y)); return r;
}
__device__ __forceinline__ float2 unpack2(u64 v) {
    float2 r; asm("mov.b64 {%0, %1}, %2;" : "=f"(r.x), "=f"(r.y) : "l"(v)); return r;
}

__device__ __forceinline__ float fsigmoid(float x) {
    return __fdividef(1.f, 1.f + __expf(-x));
}
__device__ __forceinline__ float ftanh(float x) {
    // tanh(x) = 1 - 2/(exp(2x)+1)
    return 1.f - __fdividef(2.f, __expf(2.f * x) + 1.f);
}

// =======================================================================
// GEMM: g_gi[row][c] = sum_k X[row][k] * W[c][k] + bias[c]
// rows = 262144, N = 384, K in {153,128}. 64-row tile, 256 threads,
// thread tile 8 rows x 6 col-PAIRS, packed f32x2 FMA.
// =======================================================================
__global__ void __launch_bounds__(256) gemm384(
    const float* __restrict__ Xext, int useSeq, int K,
    const float* __restrict__ W, const float* __restrict__ bias)
{
    const float* __restrict__ X = useSeq ? g_seq : Xext;
    __shared__ float xs[64][16];     // [row][kk]
    __shared__ float ws[16][386];    // [kk][col], pad 386 -> conflict-free STS + aligned pairs
    int tid = threadIdx.x;
    size_t row0 = (size_t)blockIdx.x * 64;
    int tr = (tid >> 5) * 8;     // thread row base within tile
    int tc = tid & 31;           // col-pair base; cols {2tc,2tc+1} + 64*j

    u64 acc[8][6];
#pragma unroll
    for (int r = 0; r < 8; r++)
#pragma unroll
        for (int j = 0; j < 6; j++) acc[r][j] = 0ull;

    for (int k0 = 0; k0 < K; k0 += 16) {
        // load x chunk (coalesced global, conflict-free STS)
#pragma unroll
        for (int i = tid; i < 64 * 16; i += 256) {
            int r = i >> 4, kk = i & 15;
            int k = k0 + kk;
            xs[r][kk] = (k < K) ? X[(row0 + r) * (size_t)K + k] : 0.f;
        }
        // load W chunk transposed
#pragma unroll
        for (int i = tid; i < 384 * 16; i += 256) {
            int c = i >> 4, kk = i & 15;
            int k = k0 + kk;
            ws[kk][c] = (k < K) ? W[(size_t)c * K + k] : 0.f;
        }
        __syncthreads();
#pragma unroll
        for (int kk = 0; kk < 16; kk++) {
            u64 wv[6];
#pragma unroll
            for (int j = 0; j < 6; j++)
                wv[j] = *(const u64*)&ws[kk][2 * tc + 64 * j];
#pragma unroll
            for (int r = 0; r < 8; r++) {
                u64 xp = pack2(xs[tr + r][kk]);  // broadcast LDS + pack (alu pipe)
#pragma unroll
                for (int j = 0; j < 6; j++)
                    fma2(acc[r][j], xp, wv[j]);
            }
        }
        __syncthreads();
    }
#pragma unroll
    for (int j = 0; j < 6; j++) {
        int c = 2 * tc + 64 * j;
        float2 bv = make_float2(bias[c], bias[c + 1]);
#pragma unroll
        for (int r = 0; r < 8; r++) {
            float2 v = unpack2(acc[r][j]);
            v.x += bv.x; v.y += bv.y;
            *(float2*)&g_gi[(row0 + tr + r) * (size_t)GG + c] = v;
        }
    }
}

// =======================================================================
// GRU recurrence. 128 CTAs x 8 batch rows; 384 threads.
// W_hh transposed in smem (stride 386). Hidden state stored DUPLICATED
// ({h,h} pairs) so LDS.128 directly yields packed f32x2 operands.
// Thread tile: 2 cols x 4 rows -> W re-read only 2x per step.
// =======================================================================
#define RECUR_SMEM ((128 * 386 + 8 * 128 * 2 + 8 * 384) * (int)sizeof(float))

__global__ void __launch_bounds__(384) gru_recur(
    const float* __restrict__ Whh, const float* __restrict__ bhh, int writeSeq)
{
    extern __shared__ float smem[];
    float* wp   = smem;                    // [128][386]  Whh^T, wp[k*386+g]
    float* hd   = smem + 128 * 386;        // [8][128][2] duplicated hidden
    float* ghsh = hd + 8 * 128 * 2;        // [8][384]    gh staging

    int tid = threadIdx.x;
    size_t b0 = (size_t)blockIdx.x * 8;

    // load Whh transposed (coalesced LDG along k)
    for (int idx = tid; idx < GG * HH; idx += 384) {
        int g = idx >> 7, k = idx & 127;
        wp[k * 386 + g] = Whh[idx];
    }
    for (int idx = tid; idx < 8 * HH * 2; idx += 384) hd[idx] = 0.f;

    // --- gh-compute mapping: 2 cols x 4 rows per thread ---
    int cp = tid % 192;           // col-pair id: cols {2cp, 2cp+1}
    int rg = tid / 192;           // 0..1 -> rows rg*4 .. rg*4+3

    u64 bias2 = pack2f(bhh[2 * cp], bhh[2 * cp + 1]);

    // --- gate mapping: threads < 256; 1 row x 4 units ---
    bool gate = tid < 256;
    int gr = (tid >> 5) & 7;      // 0..7
    int gj = (tid & 31) * 4;      // unit base

    float hreg[4] = {0.f, 0.f, 0.f, 0.f};
    const float* gi_base = g_gi + ((b0 + gr) * TLEN) * (size_t)GG + gj;
    float* seq_base = g_seq + ((b0 + gr) * TLEN) * (size_t)HH + gj;

    const float* wrow = wp + 2 * cp;
    const float* hrow = hd + rg * 4 * 256;   // 4 rows, each 256 floats (dup)

    __syncthreads();

    for (int t = 0; t < TLEN; t++) {
        // prefetch this step's input-projection gates (hidden under gh loop)
        float4 gir, giz, gin;
        if (gate) {
            gir = *(const float4*)(gi_base + (size_t)t * GG);
            giz = *(const float4*)(gi_base + (size_t)t * GG + 128);
            gin = *(const float4*)(gi_base + (size_t)t * GG + 256);
        }

        u64 acc[4] = {bias2, bias2, bias2, bias2};

#pragma unroll 4
        for (int k = 0; k < HH; k += 2) {
            u64 w0 = *(const u64*)(wrow + (size_t)k * 386);
            u64 w1 = *(const u64*)(wrow + (size_t)(k + 1) * 386);
#pragma unroll
            for (int r = 0; r < 4; r++) {
                // duplicated h: 16B = {h(k),h(k),h(k+1),h(k+1)} (broadcast LDS)
                ulonglong2 h2 = *(const ulonglong2*)(hrow + r * 256 + 2 * k);
                fma2(acc[r], h2.x, w0);
                fma2(acc[r], h2.y, w1);
            }
        }
#pragma unroll
        for (int r = 0; r < 4; r++)
            *(float2*)(ghsh + (rg * 4 + r) * GG + 2 * cp) = unpack2(acc[r]);
        __syncthreads();

        if (gate) {
            float4 ghr = *(float4*)(ghsh + gr * GG + gj);
            float4 ghz = *(float4*)(ghsh + gr * GG + 128 + gj);
            float4 ghn = *(float4*)(ghsh + gr * GG + 256 + gj);
            float ir[4] = {gir.x, gir.y, gir.z, gir.w};
            float iz[4] = {giz.x, giz.y, giz.z, giz.w};
            float in_[4] = {gin.x, gin.y, gin.z, gin.w};
            float hr[4] = {ghr.x, ghr.y, ghr.z, ghr.w};
            float hz[4] = {ghz.x, ghz.y, ghz.z, ghz.w};
            float hnn[4] = {ghn.x, ghn.y, ghn.z, ghn.w};
            float hn[4];
#pragma unroll
            for (int u = 0; u < 4; u++) {
                float r = fsigmoid(ir[u] + hr[u]);
                float z = fsigmoid(iz[u] + hz[u]);
                float n = ftanh(in_[u] + r * hnn[u]);
                hn[u] = (1.f - z) * n + z * hreg[u];
                hreg[u] = hn[u];
            }
            // write duplicated hidden state
            *(float4*)(hd + gr * 256 + 2 * gj) =
                make_float4(hn[0], hn[0], hn[1], hn[1]);
            *(float4*)(hd + gr * 256 + 2 * gj + 4) =
                make_float4(hn[2], hn[2], hn[3], hn[3]);
            if (writeSeq)
                *(float4*)(seq_base + (size_t)t * HH) =
                    make_float4(hn[0], hn[1], hn[2], hn[3]);
        }
        __syncthreads();
    }

    if (!writeSeq && gate)
        *(float4*)(g_hlast + (b0 + gr) * HH + gj) =
            make_float4(hreg[0], hreg[1], hreg[2], hreg[3]);
}

// =======================================================================
// Head: out[b] = sigmoid( relu(h_last[b] @ W1^T + b1) @ W2^T + b2 )
// =======================================================================
__global__ void __launch_bounds__(64) head_kernel(
    const float* __restrict__ W1, const float* __restrict__ b1,
    const float* __restrict__ W2, const float* __restrict__ b2,
    float* __restrict__ out)
{
    int b = blockIdx.x;
    int c = threadIdx.x;  // 0..63
    const float* hb = g_hlast + (size_t)b * HH;
    const float* wr = W1 + (size_t)c * HH;
    float acc = b1[c];
#pragma unroll
    for (int k = 0; k < HH; k += 4) {
        float4 hv = *(const float4*)(hb + k);
        float4 wv = *(const float4*)(wr + k);
        acc = fmaf(hv.x, wv.x, acc);
        acc = fmaf(hv.y, wv.y, acc);
        acc = fmaf(hv.z, wv.z, acc);
        acc = fmaf(hv.w, wv.w, acc);
    }
    float v = fmaxf(acc, 0.f) * W2[c];
    __shared__ float red[64];
    red[c] = v;
    __syncthreads();
    if (c == 0) {
        float s = b2[0];
#pragma unroll
        for (int i = 0; i < 64; i++) s += red[i];
        out[b] = 1.f / (1.f + expf(-s));
    }
}

// =======================================================================
extern "C" void kernel_launch(void* const* d_in, const int* in_sizes, int n_in,
                              void* d_out, int out_size)
{
    const float* x     = (const float*)d_in[0];
    const float* W_ih0 = (const float*)d_in[1];
    const float* W_hh0 = (const float*)d_in[2];
    const float* b_ih0 = (const float*)d_in[3];
    const float* b_hh0 = (const float*)d_in[4];
    const float* W_ih1 = (const float*)d_in[5];
    const float* W_hh1 = (const float*)d_in[6];
    const float* b_ih1 = (const float*)d_in[7];
    const float* b_hh1 = (const float*)d_in[8];
    const float* W1    = (const float*)d_in[9];
    const float* b1    = (const float*)d_in[10];
    const float* W2    = (const float*)d_in[11];
    const float* b2    = (const float*)d_in[12];
    float* out = (float*)d_out;

    cudaFuncSetAttribute(gru_recur, cudaFuncAttributeMaxDynamicSharedMemorySize,
                         RECUR_SMEM);

    const int M_TILES = (BSZ * TLEN) / 64;  // 4096

    // layer 0 input projection: gi0 = x @ W_ih0^T + b_ih0
    gemm384<<<M_TILES, 256>>>(x, 0, 153, W_ih0, b_ih0);
    // layer 0 recurrence -> g_seq
    gru_recur<<<128, 384, RECUR_SMEM>>>(W_hh0, b_hh0, 1);
    // layer 1 input projection: gi1 = seq0 @ W_ih1^T + b_ih1 (reuses g_gi)
    gemm384<<<M_TILES, 256>>>(nullptr, 1, 128, W_ih1, b_ih1);
    // layer 1 recurrence -> g_hlast
    gru_recur<<<128, 384, RECUR_SMEM>>>(W_hh1, b_hh1, 0);
    // classifier head
    head_kernel<<<BSZ, 64>>>(W1, b1, W2, b2, out);
}

// round 6
// speedup vs baseline: 1.3737x; 1.3041x over previous
#include <cuda_runtime.h>
#include <math.h>

#define BSZ  1024
#define TLEN 256
#define HH   128
#define GG   384   // 3*H

// -------- scratch (static device globals; no runtime allocation) --------
__device__ float g_gi[(size_t)BSZ * TLEN * GG];    // 402 MB, reused for gi0 then gi1
__device__ float g_seq[(size_t)BSZ * TLEN * HH];   // 134 MB, layer-0 output sequence
__device__ float g_hlast[(size_t)BSZ * HH];        // layer-1 final hidden

typedef unsigned long long u64;

// ---- packed f32x2 helpers (sm_100+; ptxas never auto-fuses these) ----
__device__ __forceinline__ void fma2(u64& d, u64 a, u64 b) {
    asm("fma.rn.f32x2 %0, %1, %2, %0;" : "+l"(d) : "l"(a), "l"(b));
}
__device__ __forceinline__ u64 pack2(float x) {
    u64 r; asm("mov.b64 %0, {%1, %1};" : "=l"(r) : "f"(x)); return r;
}
__device__ __forceinline__ float2 unpack2(u64 v) {
    float2 r; asm("mov.b64 {%0, %1}, %2;" : "=f"(r.x), "=f"(r.y) : "l"(v)); return r;
}

__device__ __forceinline__ float fsigmoid(float x) {
    return __fdividef(1.f, 1.f + __expf(-x));
}
__device__ __forceinline__ float ftanh(float x) {
    return 1.f - __fdividef(2.f, __expf(2.f * x) + 1.f);
}

// =======================================================================
// GEMM: g_gi[row][c] = sum_k X[row][k] * W[c][k] + bias[c]
// rows = 262144, N = 384, K in {153,128}. 64-row tile, 256 threads,
// thread tile 8 rows x 6 col-PAIRS, packed f32x2 FMA.
// =======================================================================
__global__ void __launch_bounds__(256) gemm384(
    const float* __restrict__ Xext, int useSeq, int K,
    const float* __restrict__ W, const float* __restrict__ bias)
{
    const float* __restrict__ X = useSeq ? g_seq : Xext;
    __shared__ float xs[64][16];     // [row][kk]
    __shared__ float ws[16][386];    // [kk][col], pad 386 -> conflict-free
    int tid = threadIdx.x;
    size_t row0 = (size_t)blockIdx.x * 64;
    int tr = (tid >> 5) * 8;     // thread row base within tile
    int tc = tid & 31;           // col-pair base; cols {2tc,2tc+1} + 64*j

    u64 acc[8][6];
#pragma unroll
    for (int r = 0; r < 8; r++)
#pragma unroll
        for (int j = 0; j < 6; j++) acc[r][j] = 0ull;

    for (int k0 = 0; k0 < K; k0 += 16) {
#pragma unroll
        for (int i = tid; i < 64 * 16; i += 256) {
            int r = i >> 4, kk = i & 15;
            int k = k0 + kk;
            xs[r][kk] = (k < K) ? X[(row0 + r) * (size_t)K + k] : 0.f;
        }
#pragma unroll
        for (int i = tid; i < 384 * 16; i += 256) {
            int c = i >> 4, kk = i & 15;
            int k = k0 + kk;
            ws[kk][c] = (k < K) ? W[(size_t)c * K + k] : 0.f;
        }
        __syncthreads();
#pragma unroll
        for (int kk = 0; kk < 16; kk++) {
            u64 wv[6];
#pragma unroll
            for (int j = 0; j < 6; j++)
                wv[j] = *(const u64*)&ws[kk][2 * tc + 64 * j];
#pragma unroll
            for (int r = 0; r < 8; r++) {
                u64 xp = pack2(xs[tr + r][kk]);
#pragma unroll
                for (int j = 0; j < 6; j++)
                    fma2(acc[r][j], xp, wv[j]);
            }
        }
        __syncthreads();
    }
#pragma unroll
    for (int j = 0; j < 6; j++) {
        int c = 2 * tc + 64 * j;
        float2 bv = make_float2(bias[c], bias[c + 1]);
#pragma unroll
        for (int r = 0; r < 8; r++) {
            float2 v = unpack2(acc[r][j]);
            v.x += bv.x; v.y += bv.y;
            *(float2*)&g_gi[(row0 + tr + r) * (size_t)GG + c] = v;
        }
    }
}

// =======================================================================
// GRU recurrence v3. 128 CTAs x 8 batch rows; 384 threads.
//  - matvec team: warps 0-3 (128 thr, 1/SMSP). Thread owns 3 cols x 8 rows.
//    Rows packed in pairs in the f32x2 accumulator; h stored as row-pair
//    u64 hp[4][128]; W streamed from smem exactly ONCE per step via
//    fully-coalesced LDS.32 and dup-packed in registers.
//  - gate team: warps 4-11 (256 thr). Row gr, units {lane,+32,+64,+96}.
//    gi LDGs issued before the barrier -> hidden under matvec.
// smem: wk[128][385] + hp 4KB + ghsh[384][10] = 216.6 KB
// =======================================================================
#define WK_STRIDE 385
#define GH_STRIDE 10   // floats per col in ghsh (5 u64, padded: 2-way max)
#define RECUR_SMEM ((128 * WK_STRIDE + 4 * 128 * 2 + 384 * GH_STRIDE) * (int)sizeof(float))

__global__ void __launch_bounds__(384) gru_recur(
    const float* __restrict__ Whh, const float* __restrict__ bhh, int writeSeq)
{
    extern __shared__ float smem[];
    float* wk   = smem;                        // [128][385]: wk[k*385+g] = Whh[g][k]
    float* hp   = smem + 128 * WK_STRIDE;      // [4][128] u64 row-pairs: hp[rp*256+2k+(r&1)]
    float* ghsh = hp + 4 * 128 * 2;            // [384][10]: gh[col][row] padded

    int tid = threadIdx.x;
    size_t b0 = (size_t)blockIdx.x * 8;

    // load Whh transposed: conflict-free (stride 385)
    for (int idx = tid; idx < GG * HH; idx += 384) {
        int g = idx >> 7, k = idx & 127;
        wk[k * WK_STRIDE + g] = Whh[idx];
    }
    for (int idx = tid; idx < 4 * 128 * 2; idx += 384) hp[idx] = 0.f;

    const bool mv = tid < 128;                 // matvec team
    int col = tid;                             // cols col, col+128, col+256

    u64 bias2[3];
    if (mv) {
#pragma unroll
        for (int c = 0; c < 3; c++) bias2[c] = pack2(bhh[col + 128 * c]);
    }

    // gate team mapping
    int t2 = tid - 128;
    int gr = t2 >> 5;                          // 0..7 (valid when !mv)
    int gl = t2 & 31;                          // units gl + 32u

    float hreg[4] = {0.f, 0.f, 0.f, 0.f};
    const float* gi_base = g_gi + ((b0 + gr) * TLEN) * (size_t)GG + gl;
    float* seq_base = g_seq + ((b0 + gr) * TLEN) * (size_t)HH + gl;

    __syncthreads();

    for (int t = 0; t < TLEN; t++) {
        float gi_v[12];
        if (!mv) {
            // issue gi LDGs before the barrier: latency hidden under matvec
            const float* gp = gi_base + (size_t)t * GG;
#pragma unroll
            for (int gidx = 0; gidx < 3; gidx++)
#pragma unroll
                for (int u = 0; u < 4; u++)
                    gi_v[gidx * 4 + u] = gp[gidx * 128 + u * 32];
        } else {
            u64 acc[4][3];
#pragma unroll
            for (int rp = 0; rp < 4; rp++)
#pragma unroll
                for (int c = 0; c < 3; c++) acc[rp][c] = bias2[c];

#pragma unroll 4
            for (int k = 0; k < HH; k += 2) {
                u64 wd0[3], wd1[3];
#pragma unroll
                for (int c = 0; c < 3; c++) {
                    wd0[c] = pack2(wk[k * WK_STRIDE + col + 128 * c]);
                    wd1[c] = pack2(wk[(k + 1) * WK_STRIDE + col + 128 * c]);
                }
#pragma unroll
                for (int rp = 0; rp < 4; rp++) {
                    ulonglong2 h2 = *(const ulonglong2*)(hp + rp * 256 + 2 * k);
#pragma unroll
                    for (int c = 0; c < 3; c++) {
                        fma2(acc[rp][c], h2.x, wd0[c]);
                        fma2(acc[rp][c], h2.y, wd1[c]);
                    }
                }
            }
            // stage gh: ghsh[col][rp] as u64 pairs {row 2rp, 2rp+1}
#pragma unroll
            for (int c = 0; c < 3; c++)
#pragma unroll
                for (int rp = 0; rp < 4; rp++)
                    *(u64*)(ghsh + (col + 128 * c) * GH_STRIDE + 2 * rp) = acc[rp][c];
        }
        __syncthreads();

        if (!mv) {
            int rsel = (gr >> 1) * 2 + (gr & 1);
            float hn[4];
#pragma unroll
            for (int u = 0; u < 4; u++) {
                int j = gl + 32 * u;
                float ghr = ghsh[j * GH_STRIDE + rsel];
                float ghz = ghsh[(j + 128) * GH_STRIDE + rsel];
                float ghn = ghsh[(j + 256) * GH_STRIDE + rsel];
                float r = fsigmoid(gi_v[u] + ghr);
                float z = fsigmoid(gi_v[4 + u] + ghz);
                float n = ftanh(gi_v[8 + u] + r * ghn);
                hn[u] = (1.f - z) * n + z * hreg[u];
                hreg[u] = hn[u];
            }
            // write new h into row-pair layout: hp[(gr/2)*256 + 2j + (gr&1)]
            int rp = gr >> 1, half = gr & 1;
#pragma unroll
            for (int u = 0; u < 4; u++) {
                int j = gl + 32 * u;
                hp[rp * 256 + 2 * j + half] = hn[u];
            }
            if (writeSeq) {
                float* sp = seq_base + (size_t)t * HH;
#pragma unroll
                for (int u = 0; u < 4; u++) sp[u * 32] = hn[u];
            }
        }
        __syncthreads();
    }

    if (!writeSeq && !mv) {
        float* hl = g_hlast + (b0 + gr) * HH + gl;
#pragma unroll
        for (int u = 0; u < 4; u++) hl[u * 32] = hreg[u];
    }
}

// =======================================================================
// Head: out[b] = sigmoid( relu(h_last[b] @ W1^T + b1) @ W2^T + b2 )
// =======================================================================
__global__ void __launch_bounds__(64) head_kernel(
    const float* __restrict__ W1, const float* __restrict__ b1,
    const float* __restrict__ W2, const float* __restrict__ b2,
    float* __restrict__ out)
{
    int b = blockIdx.x;
    int c = threadIdx.x;  // 0..63
    const float* hb = g_hlast + (size_t)b * HH;
    const float* wr = W1 + (size_t)c * HH;
    float acc = b1[c];
#pragma unroll
    for (int k = 0; k < HH; k += 4) {
        float4 hv = *(const float4*)(hb + k);
        float4 wv = *(const float4*)(wr + k);
        acc = fmaf(hv.x, wv.x, acc);
        acc = fmaf(hv.y, wv.y, acc);
        acc = fmaf(hv.z, wv.z, acc);
        acc = fmaf(hv.w, wv.w, acc);
    }
    float v = fmaxf(acc, 0.f) * W2[c];
    __shared__ float red[64];
    red[c] = v;
    __syncthreads();
    if (c == 0) {
        float s = b2[0];
#pragma unroll
        for (int i = 0; i < 64; i++) s += red[i];
        out[b] = 1.f / (1.f + expf(-s));
    }
}

// =======================================================================
extern "C" void kernel_launch(void* const* d_in, const int* in_sizes, int n_in,
                              void* d_out, int out_size)
{
    const float* x     = (const float*)d_in[0];
    const float* W_ih0 = (const float*)d_in[1];
    const float* W_hh0 = (const float*)d_in[2];
    const float* b_ih0 = (const float*)d_in[3];
    const float* b_hh0 = (const float*)d_in[4];
    const float* W_ih1 = (const float*)d_in[5];
    const float* W_hh1 = (const float*)d_in[6];
    const float* b_ih1 = (const float*)d_in[7];
    const float* b_hh1 = (const float*)d_in[8];
    const float* W1    = (const float*)d_in[9];
    const float* b1    = (const float*)d_in[10];
    const float* W2    = (const float*)d_in[11];
    const float* b2    = (const float*)d_in[12];
    float* out = (float*)d_out;

    cudaFuncSetAttribute(gru_recur, cudaFuncAttributeMaxDynamicSharedMemorySize,
                         RECUR_SMEM);

    const int M_TILES = (BSZ * TLEN) / 64;  // 4096

    gemm384<<<M_TILES, 256>>>(x, 0, 153, W_ih0, b_ih0);
    gru_recur<<<128, 384, RECUR_SMEM>>>(W_hh0, b_hh0, 1);
    gemm384<<<M_TILES, 256>>>(nullptr, 1, 128, W_ih1, b_ih1);
    gru_recur<<<128, 384, RECUR_SMEM>>>(W_hh1, b_hh1, 0);
    head_kernel<<<BSZ, 64>>>(W1, b1, W2, b2, out);
}